// round 16
// baseline (speedup 1.0000x reference)
#include <cuda_runtime.h>
#include <cuda_fp16.h>
#include <math.h>
#include <stdint.h>

#define D_TOT   147456
#define N_MEM   6
#define NPX     4096
#define SRB     144                 // row stride bytes (64 ic halves + 16 pad)
#define WB      9216u               // W tile: 64 rows * 144
#define OFF_X   18432u              // after 2-deep W ring
#define SM_BYTES 56448              // 2*WB + 264*144

// ---------------- device scratch (no allocation allowed) -------------------
__device__ float  g_minmax[2] = {-INFINITY, INFINITY};
__device__ __half g_w2[N_MEM * 9 * 128 * 128];  // [n][tap][oc][ic] fp16
__device__ __half g_xh[48 * NPX * 128];         // [s][px][ic] NHWC fp16

// ---------------- helpers ---------------------------------------------------
__device__ __forceinline__ uint32_t smem_u32(const void* p) {
    uint32_t a;
    asm("{ .reg .u64 t; cvta.to.shared.u64 t, %1; cvt.u32.u64 %0, t; }"
        : "=r"(a) : "l"(p));
    return a;
}
__device__ __forceinline__ void cp16(uint32_t dst, const void* src, uint32_t sz) {
    asm volatile("cp.async.cg.shared.global [%0], [%1], 16, %2;"
                 :: "r"(dst), "l"(src), "r"(sz) : "memory");
}
__device__ __forceinline__ void ldm4(uint32_t& r0, uint32_t& r1,
                                     uint32_t& r2, uint32_t& r3, uint32_t a) {
    asm volatile("ldmatrix.sync.aligned.m8n8.x4.shared.b16 {%0,%1,%2,%3}, [%4];"
                 : "=r"(r0), "=r"(r1), "=r"(r2), "=r"(r3) : "r"(a));
}
__device__ __forceinline__ void mma16(float4& d, const uint32_t* a,
                                      uint32_t b0, uint32_t b1) {
    asm volatile(
        "mma.sync.aligned.m16n8k16.row.col.f32.f16.f16.f32 "
        "{%0,%1,%2,%3},{%4,%5,%6,%7},{%8,%9},{%0,%1,%2,%3};"
        : "+f"(d.x), "+f"(d.y), "+f"(d.z), "+f"(d.w)
        : "r"(a[0]), "r"(a[1]), "r"(a[2]), "r"(a[3]), "r"(b0), "r"(b1));
}

// ---------------------------------------------------------------------------
// Stage 0: global max/min of U — latency-optimal: one float4 per thread,
// all loads independent, then warp shuffle + 2 atomics per warp.
// 864 blocks * 256 threads * 4 floats = 884736 = 6*147456 exactly.
// ---------------------------------------------------------------------------
__device__ __forceinline__ void atomicMaxF(float* a, float v) {
    if (v >= 0.f) atomicMax((int*)a, __float_as_int(v));
    else          atomicMin((unsigned int*)a, __float_as_uint(v));
}
__device__ __forceinline__ void atomicMinF(float* a, float v) {
    if (v >= 0.f) atomicMin((int*)a, __float_as_int(v));
    else          atomicMax((unsigned int*)a, __float_as_uint(v));
}

__global__ void reduce_minmax_kernel(const float4* __restrict__ U4) {
    int i = blockIdx.x * 256 + threadIdx.x;
    float4 v = U4[i];
    float mx = fmaxf(fmaxf(v.x, v.y), fmaxf(v.z, v.w));
    float mn = fminf(fminf(v.x, v.y), fminf(v.z, v.w));
#pragma unroll
    for (int o = 16; o; o >>= 1) {
        mx = fmaxf(mx, __shfl_xor_sync(0xffffffffu, mx, o));
        mn = fminf(mn, __shfl_xor_sync(0xffffffffu, mn, o));
    }
    if ((threadIdx.x & 31) == 0) { atomicMaxF(&g_minmax[0], mx); atomicMinF(&g_minmax[1], mn); }
}

// ---------------------------------------------------------------------------
// Stage 1 (fused prep): blocks [0,576) do compute_w (ALU-bound);
// blocks [576,...) do the NCHW->NHWC fp16 transpose (DRAM-bound).
// ---------------------------------------------------------------------------
#define WGRID 576                    // D_TOT / 256

__device__ __forceinline__ float stable_sigmoid(float x) {
    if (x >= 0.f) return 1.f / (1.f + __expf(-x));
    float e = __expf(x); return e / (1.f + e);
}
__device__ __forceinline__ float gatef(float uu, float b) {
    float g  = __logf(uu / (1.f - uu));
    float bs = stable_sigmoid(g + b);
    float t  = __fadd_rn(__fmul_rn(bs, 1.4f), -0.2f);
    return fminf(fmaxf(t, 0.f), 1.f);
}

__global__ void prep_kernel(const float* __restrict__ U,
                            const float* __restrict__ bp,
                            const float* __restrict__ uu,
                            const float* __restrict__ x) {
    __shared__ float t[64][33];
    int tid = threadIdx.x;

    if (blockIdx.x < WGRID) {
        // ---------------- compute_w ----------------
        int d = blockIdx.x * 256 + tid;

        float s1 = (g_minmax[0] - g_minmax[1]) / 3.0f;
        float s2 = s1 / 5.0f;

        float Uv[N_MEM], v1[N_MEM];
        float m1 = 0.f;
#pragma unroll
        for (int nn = 0; nn < N_MEM; nn++) {
            Uv[nn] = U[nn * D_TOT + d];
            v1[nn] = s1 * rintf(Uv[nn] / s1);
            m1 += v1[nn];
        }
        m1 *= (1.0f / 6.0f);

        float g1 = gatef(uu[6 * D_TOT + d], bp[6 * D_TOT + d]);

        int oc  = d / 1152;
        int rem = d - oc * 1152;
        int ic  = rem / 9;
        int tap = rem - ic * 9;
        size_t base = ((size_t)tap * 128 + oc) * 128 + ic;

#pragma unroll
        for (int nn = 0; nn < N_MEM; nn++) {
            float v2 = s2 * rintf((Uv[nn] - m1) / s2);
            float g0 = gatef(uu[nn * D_TOT + d], bp[nn * D_TOT + d]);
            float w  = v1[nn] * g0 + ((g0 > 0.f) ? v2 * g1 : 0.f);
            g_w2[(size_t)nn * (9 * 16384) + base] = __float2half_rn(w);
        }
    } else {
        // ---------------- transpose ----------------
        int bid = blockIdx.x - WGRID;       // 0 .. 48*256-1
        int s   = bid >> 8;
        int r   = bid & 255;
        int px0 = (r >> 1) * 32;
        int ic0 = (r & 1) * 64;
        int tx = tid & 31, ty = tid >> 5;

        const float* xs = x + (size_t)s * 128 * NPX;
#pragma unroll
        for (int j = 0; j < 8; j++) {
            int icl = ty + j * 8;
            t[icl][tx] = xs[(size_t)(ic0 + icl) * NPX + px0 + tx];
        }
        __syncthreads();
        __half* xd = g_xh + (size_t)s * NPX * 128;
#pragma unroll
        for (int j = 0; j < 4; j++) {
            int pxl = ty + j * 8;
            __half2 v = __floats2half2_rn(t[2 * tx][pxl], t[2 * tx + 1][pxl]);
            *(__half2*)&xd[(size_t)(px0 + pxl) * 128 + ic0 + 2 * tx] = v;
        }
    }
}

// ---------------------------------------------------------------------------
// Stage 2: fp16 mma conv (R13-validated), 4 CTAs/SM, X loaded once/ic-half.
//   CTA: 64 oc x 128 px (2 img rows). X: haloed [4 rows][66 px][64 ic];
//   taps = ldmatrix address shifts. W: 2-deep cp.async ring.
// ---------------------------------------------------------------------------
__device__ __forceinline__ void issue_w(int stg, uint32_t sbase, int tid,
                                        const __half* wbase, int ocg) {
    int h = stg / 9, tap = stg - h * 9;
    const __half* wsrc = wbase + (size_t)tap * 16384 + ocg * 64 * 128 + h * 64;
    uint32_t wdst = sbase + (uint32_t)(stg & 1) * WB;
#pragma unroll
    for (int i = 0; i < 4; i++) {                   // 64 rows x 8 chunks
        int idx = tid + i * 128;
        int row = idx >> 3, j = idx & 7;
        cp16(wdst + row * SRB + j * 16, wsrc + (size_t)row * 128 + j * 8, 16);
    }
    asm volatile("cp.async.commit_group;" ::: "memory");
}

__device__ __forceinline__ void issue_x(int h, uint32_t sbase, int tid,
                                        const __half* xbase, int y0) {
    // 264 px-entries (4 rows x 66 cols) x 8 chunks = 2112 cp16
#pragma unroll
    for (int i = 0; i < 17; i++) {
        int idx = tid + i * 128;
        if (idx < 2112) {
            int p = idx >> 3, j = idx & 7;
            int yy = p / 66, xx = p - yy * 66;
            int gy = y0 + yy - 1;
            int gx = xx - 1;
            bool ok = ((unsigned)gy < 64u) && ((unsigned)gx < 64u);
            const __half* src = xbase + (size_t)(ok ? gy * 64 + gx : 0) * 128
                                + h * 64 + j * 8;
            cp16(sbase + OFF_X + p * SRB + j * 16, src, ok ? 16u : 0u);
        }
    }
    asm volatile("cp.async.commit_group;" ::: "memory");
}

__global__ __launch_bounds__(128, 4)
void conv_kernel(float* __restrict__ out) {
    extern __shared__ __half smh[];
    uint32_t sbase = smem_u32(smh);

    const int tid = threadIdx.x;
    const int y0  = blockIdx.x * 2;          // 2 image rows (128 px)
    const int ocg = blockIdx.y;              // oc half (64 oc)
    const int s   = blockIdx.z;
    const int n   = s % N_MEM;

    const int w   = tid >> 5;
    const int l   = tid & 31;
    const int grp = l >> 2, thr = l & 3;
    const int ocb = (w & 1) * 32;
    const int pxb = (w >> 1) * 64;

    const uint32_t aoff = (uint32_t)((ocb + (l & 15)) * SRB + (l >> 4) * 16);
    const int px  = pxb + (l & 7) + ((l >> 4) & 1) * 8;
    const uint32_t boff = OFF_X
        + (uint32_t)(((1 + (px >> 6)) * 66 + (px & 63) + 1) * SRB
                     + ((l >> 3) & 1) * 16);

    const __half* wbase = g_w2 + (size_t)n * 9 * 16384;
    const __half* xbase = g_xh + (size_t)s * NPX * 128;

    float4 acc[2][8];
#pragma unroll
    for (int i = 0; i < 2; i++)
#pragma unroll
        for (int j = 0; j < 8; j++) acc[i][j] = make_float4(0.f, 0.f, 0.f, 0.f);

    issue_x(0, sbase, tid, xbase, y0);       // group X0
    issue_w(0, sbase, tid, wbase, ocg);      // group W0
    issue_w(1, sbase, tid, wbase, ocg);      // group W1

#pragma unroll
    for (int st = 0; st < 18; st++) {
        if (st < 17) asm volatile("cp.async.wait_group 1;" ::: "memory");
        else         asm volatile("cp.async.wait_group 0;" ::: "memory");
        __syncthreads();

        int h   = st / 9, tap = st - h * 9;
        (void)h;
        int dy  = tap / 3 - 1, dx = tap % 3 - 1;
        int toff = (dy * 66 + dx) * SRB;

        uint32_t aA = sbase + (uint32_t)(st & 1) * WB + aoff;
        uint32_t aB = sbase + boff + toff;

#pragma unroll
        for (int ks = 0; ks < 4; ks++) {            // 4 k16 blocks in K=64
            uint32_t a[2][4];
#pragma unroll
            for (int mt = 0; mt < 2; mt++)
                ldm4(a[mt][0], a[mt][1], a[mt][2], a[mt][3],
                     aA + mt * 16 * SRB + ks * 32);
#pragma unroll
            for (int ntp = 0; ntp < 4; ntp++) {
                uint32_t b0, b1, b2, b3;
                ldm4(b0, b1, b2, b3, aB + ntp * 16 * SRB + ks * 32);
#pragma unroll
                for (int mt = 0; mt < 2; mt++) {
                    mma16(acc[mt][2 * ntp],     a[mt], b0, b1);
                    mma16(acc[mt][2 * ntp + 1], a[mt], b2, b3);
                }
            }
        }
        __syncthreads();                       // all reads of W buf + X done
        if (st == 8) issue_x(1, sbase, tid, xbase, y0);   // swap ic-half
        if (st + 2 < 18) issue_w(st + 2, sbase, tid, wbase, ocg);
    }

    // epilogue: float2 stores, NCHW output
    float* ob = out + ((size_t)s * 128 + ocg * 64) * NPX;
#pragma unroll
    for (int mt = 0; mt < 2; mt++) {
        int oc = ocb + mt * 16 + grp;
#pragma unroll
        for (int nt = 0; nt < 8; nt++) {
            int p2 = pxb + nt * 8 + 2 * thr;
            float* op = ob + (size_t)oc * NPX + (y0 + (p2 >> 6)) * 64 + (p2 & 63);
            float4 d = acc[mt][nt];
            *(float2*)op = make_float2(d.x, d.y);
            *(float2*)(op + 8 * NPX) = make_float2(d.z, d.w);
        }
    }
}

// ---------------------------------------------------------------------------
extern "C" void kernel_launch(void* const* d_in, const int* in_sizes, int n_in,
                              void* d_out, int out_size) {
    const float* x  = (const float*)d_in[0];   // (48,128,64,64)
    const float* U  = (const float*)d_in[1];
    const float* bp = (const float*)d_in[2];
    const float* u  = (const float*)d_in[3];
    float* out = (float*)d_out;

    cudaFuncSetAttribute(conv_kernel, cudaFuncAttributeMaxDynamicSharedMemorySize, SM_BYTES);

    reduce_minmax_kernel<<<864, 256>>>((const float4*)U);
    prep_kernel<<<WGRID + 48 * 256, 256>>>(U, bp, u, x);

    conv_kernel<<<dim3(32, 2, 48), 128, SM_BYTES>>>(out);
}

// round 17
// speedup vs baseline: 1.0373x; 1.0373x over previous
#include <cuda_runtime.h>
#include <cuda_fp16.h>
#include <math.h>
#include <stdint.h>

#define D_TOT   147456
#define N_MEM   6
#define NPX     4096
#define SRB     144                 // row stride bytes (64 ic halves + 16 pad)
#define WB      9216u               // W tile: 64 rows * 144
#define OFF_X   18432u              // after 2-deep W ring
#define SM_BYTES 56448              // 2*WB + 264*144

// ---------------- device scratch (no allocation allowed) -------------------
__device__ float  g_minmax[2] = {-INFINITY, INFINITY};
__device__ __half g_w2[N_MEM * 9 * 128 * 128];  // [n][tap][oc][ic] fp16
__device__ __half g_xh[48 * NPX * 128];         // [s][px][ic] NHWC fp16

// ---------------- helpers ---------------------------------------------------
__device__ __forceinline__ uint32_t smem_u32(const void* p) {
    uint32_t a;
    asm("{ .reg .u64 t; cvta.to.shared.u64 t, %1; cvt.u32.u64 %0, t; }"
        : "=r"(a) : "l"(p));
    return a;
}
__device__ __forceinline__ void cp16(uint32_t dst, const void* src, uint32_t sz) {
    asm volatile("cp.async.cg.shared.global [%0], [%1], 16, %2;"
                 :: "r"(dst), "l"(src), "r"(sz) : "memory");
}
__device__ __forceinline__ void ldm4(uint32_t& r0, uint32_t& r1,
                                     uint32_t& r2, uint32_t& r3, uint32_t a) {
    asm volatile("ldmatrix.sync.aligned.m8n8.x4.shared.b16 {%0,%1,%2,%3}, [%4];"
                 : "=r"(r0), "=r"(r1), "=r"(r2), "=r"(r3) : "r"(a));
}
__device__ __forceinline__ void mma16(float4& d, const uint32_t* a,
                                      uint32_t b0, uint32_t b1) {
    asm volatile(
        "mma.sync.aligned.m16n8k16.row.col.f32.f16.f16.f32 "
        "{%0,%1,%2,%3},{%4,%5,%6,%7},{%8,%9},{%0,%1,%2,%3};"
        : "+f"(d.x), "+f"(d.y), "+f"(d.z), "+f"(d.w)
        : "r"(a[0]), "r"(a[1]), "r"(a[2]), "r"(a[3]), "r"(b0), "r"(b1));
}

// ---------------------------------------------------------------------------
// Stage 0: global max/min of U.
//   216 blocks x 256 thr x 4 independent float4 = 884736 floats exactly.
//   Warp shuffle -> smem -> block fold -> ONE atomic pair per block
//   (432 atomics total; R16 showed duration scales with atomic count).
// ---------------------------------------------------------------------------
__device__ __forceinline__ void atomicMaxF(float* a, float v) {
    if (v >= 0.f) atomicMax((int*)a, __float_as_int(v));
    else          atomicMin((unsigned int*)a, __float_as_uint(v));
}
__device__ __forceinline__ void atomicMinF(float* a, float v) {
    if (v >= 0.f) atomicMin((int*)a, __float_as_int(v));
    else          atomicMax((unsigned int*)a, __float_as_uint(v));
}

__global__ void reduce_minmax_kernel(const float4* __restrict__ U4) {
    __shared__ float smx[8], smn[8];
    int tid = threadIdx.x;
    int base = blockIdx.x * 1024 + tid;

    float4 v0 = U4[base];
    float4 v1 = U4[base + 256];
    float4 v2 = U4[base + 512];
    float4 v3 = U4[base + 768];

    float mx = fmaxf(fmaxf(fmaxf(v0.x, v0.y), fmaxf(v0.z, v0.w)),
                     fmaxf(fmaxf(v1.x, v1.y), fmaxf(v1.z, v1.w)));
    mx = fmaxf(mx, fmaxf(fmaxf(fmaxf(v2.x, v2.y), fmaxf(v2.z, v2.w)),
                         fmaxf(fmaxf(v3.x, v3.y), fmaxf(v3.z, v3.w))));
    float mn = fminf(fminf(fminf(v0.x, v0.y), fminf(v0.z, v0.w)),
                     fminf(fminf(v1.x, v1.y), fminf(v1.z, v1.w)));
    mn = fminf(mn, fminf(fminf(fminf(v2.x, v2.y), fminf(v2.z, v2.w)),
                         fminf(fminf(v3.x, v3.y), fminf(v3.z, v3.w))));

#pragma unroll
    for (int o = 16; o; o >>= 1) {
        mx = fmaxf(mx, __shfl_xor_sync(0xffffffffu, mx, o));
        mn = fminf(mn, __shfl_xor_sync(0xffffffffu, mn, o));
    }
    if ((tid & 31) == 0) { smx[tid >> 5] = mx; smn[tid >> 5] = mn; }
    __syncthreads();
    if (tid < 32) {
        float bmx = smx[tid & 7], bmn = smn[tid & 7];
#pragma unroll
        for (int o = 4; o; o >>= 1) {
            bmx = fmaxf(bmx, __shfl_xor_sync(0xffffffffu, bmx, o));
            bmn = fminf(bmn, __shfl_xor_sync(0xffffffffu, bmn, o));
        }
        if (tid == 0) { atomicMaxF(&g_minmax[0], bmx); atomicMinF(&g_minmax[1], bmn); }
    }
}

// ---------------------------------------------------------------------------
// Stage 1 (fused prep): blocks [0,576) do compute_w (ALU-bound);
// blocks [576,...) do the NCHW->NHWC fp16 transpose (DRAM-bound).
// ---------------------------------------------------------------------------
#define WGRID 576                    // D_TOT / 256

__device__ __forceinline__ float stable_sigmoid(float x) {
    if (x >= 0.f) return 1.f / (1.f + __expf(-x));
    float e = __expf(x); return e / (1.f + e);
}
__device__ __forceinline__ float gatef(float uu, float b) {
    float g  = __logf(uu / (1.f - uu));
    float bs = stable_sigmoid(g + b);
    float t  = __fadd_rn(__fmul_rn(bs, 1.4f), -0.2f);
    return fminf(fmaxf(t, 0.f), 1.f);
}

__global__ void prep_kernel(const float* __restrict__ U,
                            const float* __restrict__ bp,
                            const float* __restrict__ uu,
                            const float* __restrict__ x) {
    __shared__ float t[64][33];
    int tid = threadIdx.x;

    if (blockIdx.x < WGRID) {
        // ---------------- compute_w ----------------
        int d = blockIdx.x * 256 + tid;

        float s1 = (g_minmax[0] - g_minmax[1]) / 3.0f;
        float s2 = s1 / 5.0f;

        float Uv[N_MEM], v1[N_MEM];
        float m1 = 0.f;
#pragma unroll
        for (int nn = 0; nn < N_MEM; nn++) {
            Uv[nn] = U[nn * D_TOT + d];
            v1[nn] = s1 * rintf(Uv[nn] / s1);
            m1 += v1[nn];
        }
        m1 *= (1.0f / 6.0f);

        float g1 = gatef(uu[6 * D_TOT + d], bp[6 * D_TOT + d]);

        int oc  = d / 1152;
        int rem = d - oc * 1152;
        int ic  = rem / 9;
        int tap = rem - ic * 9;
        size_t base = ((size_t)tap * 128 + oc) * 128 + ic;

#pragma unroll
        for (int nn = 0; nn < N_MEM; nn++) {
            float v2 = s2 * rintf((Uv[nn] - m1) / s2);
            float g0 = gatef(uu[nn * D_TOT + d], bp[nn * D_TOT + d]);
            float w  = v1[nn] * g0 + ((g0 > 0.f) ? v2 * g1 : 0.f);
            g_w2[(size_t)nn * (9 * 16384) + base] = __float2half_rn(w);
        }
    } else {
        // ---------------- transpose ----------------
        int bid = blockIdx.x - WGRID;       // 0 .. 48*256-1
        int s   = bid >> 8;
        int r   = bid & 255;
        int px0 = (r >> 1) * 32;
        int ic0 = (r & 1) * 64;
        int tx = tid & 31, ty = tid >> 5;

        const float* xs = x + (size_t)s * 128 * NPX;
#pragma unroll
        for (int j = 0; j < 8; j++) {
            int icl = ty + j * 8;
            t[icl][tx] = xs[(size_t)(ic0 + icl) * NPX + px0 + tx];
        }
        __syncthreads();
        __half* xd = g_xh + (size_t)s * NPX * 128;
#pragma unroll
        for (int j = 0; j < 4; j++) {
            int pxl = ty + j * 8;
            __half2 v = __floats2half2_rn(t[2 * tx][pxl], t[2 * tx + 1][pxl]);
            *(__half2*)&xd[(size_t)(px0 + pxl) * 128 + ic0 + 2 * tx] = v;
        }
    }
}

// ---------------------------------------------------------------------------
// Stage 2: fp16 mma conv (R13-validated), 4 CTAs/SM, X loaded once/ic-half.
//   CTA: 64 oc x 128 px (2 img rows). X: haloed [4 rows][66 px][64 ic];
//   taps = ldmatrix address shifts. W: 2-deep cp.async ring.
// ---------------------------------------------------------------------------
__device__ __forceinline__ void issue_w(int stg, uint32_t sbase, int tid,
                                        const __half* wbase, int ocg) {
    int h = stg / 9, tap = stg - h * 9;
    const __half* wsrc = wbase + (size_t)tap * 16384 + ocg * 64 * 128 + h * 64;
    uint32_t wdst = sbase + (uint32_t)(stg & 1) * WB;
#pragma unroll
    for (int i = 0; i < 4; i++) {                   // 64 rows x 8 chunks
        int idx = tid + i * 128;
        int row = idx >> 3, j = idx & 7;
        cp16(wdst + row * SRB + j * 16, wsrc + (size_t)row * 128 + j * 8, 16);
    }
    asm volatile("cp.async.commit_group;" ::: "memory");
}

__device__ __forceinline__ void issue_x(int h, uint32_t sbase, int tid,
                                        const __half* xbase, int y0) {
    // 264 px-entries (4 rows x 66 cols) x 8 chunks = 2112 cp16
#pragma unroll
    for (int i = 0; i < 17; i++) {
        int idx = tid + i * 128;
        if (idx < 2112) {
            int p = idx >> 3, j = idx & 7;
            int yy = p / 66, xx = p - yy * 66;
            int gy = y0 + yy - 1;
            int gx = xx - 1;
            bool ok = ((unsigned)gy < 64u) && ((unsigned)gx < 64u);
            const __half* src = xbase + (size_t)(ok ? gy * 64 + gx : 0) * 128
                                + h * 64 + j * 8;
            cp16(sbase + OFF_X + p * SRB + j * 16, src, ok ? 16u : 0u);
        }
    }
    asm volatile("cp.async.commit_group;" ::: "memory");
}

__global__ __launch_bounds__(128, 4)
void conv_kernel(float* __restrict__ out) {
    extern __shared__ __half smh[];
    uint32_t sbase = smem_u32(smh);

    const int tid = threadIdx.x;
    const int y0  = blockIdx.x * 2;          // 2 image rows (128 px)
    const int ocg = blockIdx.y;              // oc half (64 oc)
    const int s   = blockIdx.z;
    const int n   = s % N_MEM;

    const int w   = tid >> 5;
    const int l   = tid & 31;
    const int grp = l >> 2, thr = l & 3;
    const int ocb = (w & 1) * 32;
    const int pxb = (w >> 1) * 64;

    const uint32_t aoff = (uint32_t)((ocb + (l & 15)) * SRB + (l >> 4) * 16);
    const int px  = pxb + (l & 7) + ((l >> 4) & 1) * 8;
    const uint32_t boff = OFF_X
        + (uint32_t)(((1 + (px >> 6)) * 66 + (px & 63) + 1) * SRB
                     + ((l >> 3) & 1) * 16);

    const __half* wbase = g_w2 + (size_t)n * 9 * 16384;
    const __half* xbase = g_xh + (size_t)s * NPX * 128;

    float4 acc[2][8];
#pragma unroll
    for (int i = 0; i < 2; i++)
#pragma unroll
        for (int j = 0; j < 8; j++) acc[i][j] = make_float4(0.f, 0.f, 0.f, 0.f);

    issue_x(0, sbase, tid, xbase, y0);       // group X0
    issue_w(0, sbase, tid, wbase, ocg);      // group W0
    issue_w(1, sbase, tid, wbase, ocg);      // group W1

#pragma unroll
    for (int st = 0; st < 18; st++) {
        if (st < 17) asm volatile("cp.async.wait_group 1;" ::: "memory");
        else         asm volatile("cp.async.wait_group 0;" ::: "memory");
        __syncthreads();

        int h   = st / 9, tap = st - h * 9;
        (void)h;
        int dy  = tap / 3 - 1, dx = tap % 3 - 1;
        int toff = (dy * 66 + dx) * SRB;

        uint32_t aA = sbase + (uint32_t)(st & 1) * WB + aoff;
        uint32_t aB = sbase + boff + toff;

#pragma unroll
        for (int ks = 0; ks < 4; ks++) {            // 4 k16 blocks in K=64
            uint32_t a[2][4];
#pragma unroll
            for (int mt = 0; mt < 2; mt++)
                ldm4(a[mt][0], a[mt][1], a[mt][2], a[mt][3],
                     aA + mt * 16 * SRB + ks * 32);
#pragma unroll
            for (int ntp = 0; ntp < 4; ntp++) {
                uint32_t b0, b1, b2, b3;
                ldm4(b0, b1, b2, b3, aB + ntp * 16 * SRB + ks * 32);
#pragma unroll
                for (int mt = 0; mt < 2; mt++) {
                    mma16(acc[mt][2 * ntp],     a[mt], b0, b1);
                    mma16(acc[mt][2 * ntp + 1], a[mt], b2, b3);
                }
            }
        }
        __syncthreads();                       // all reads of W buf + X done
        if (st == 8) issue_x(1, sbase, tid, xbase, y0);   // swap ic-half
        if (st + 2 < 18) issue_w(st + 2, sbase, tid, wbase, ocg);
    }

    // epilogue: float2 stores, NCHW output
    float* ob = out + ((size_t)s * 128 + ocg * 64) * NPX;
#pragma unroll
    for (int mt = 0; mt < 2; mt++) {
        int oc = ocb + mt * 16 + grp;
#pragma unroll
        for (int nt = 0; nt < 8; nt++) {
            int p2 = pxb + nt * 8 + 2 * thr;
            float* op = ob + (size_t)oc * NPX + (y0 + (p2 >> 6)) * 64 + (p2 & 63);
            float4 d = acc[mt][nt];
            *(float2*)op = make_float2(d.x, d.y);
            *(float2*)(op + 8 * NPX) = make_float2(d.z, d.w);
        }
    }
}

// ---------------------------------------------------------------------------
extern "C" void kernel_launch(void* const* d_in, const int* in_sizes, int n_in,
                              void* d_out, int out_size) {
    const float* x  = (const float*)d_in[0];   // (48,128,64,64)
    const float* U  = (const float*)d_in[1];
    const float* bp = (const float*)d_in[2];
    const float* u  = (const float*)d_in[3];
    float* out = (float*)d_out;

    cudaFuncSetAttribute(conv_kernel, cudaFuncAttributeMaxDynamicSharedMemorySize, SM_BYTES);

    reduce_minmax_kernel<<<216, 256>>>((const float4*)U);
    prep_kernel<<<WGRID + 48 * 256, 256>>>(U, bp, u, x);

    conv_kernel<<<dim3(32, 2, 48), 128, SM_BYTES>>>(out);
}